// round 6
// baseline (speedup 1.0000x reference)
#include <cuda_runtime.h>

// StereoDenoiser: B=8, C=3, H=1024, W=1920, fp32.
//   disp  = clip(depth*128, 0, 128)            [B,H,W]
//   warped_r = bilinear_x(img_r, x = w - disp) (border clamp)
//   warped_l = bilinear_x(img_l, x = w + disp)
//   out_l = (img_l + warped_r)*0.5 ; out_r = (img_r + warped_l)*0.5
// Output buffer: [out_l | out_r], each B*C*H*W floats.
//
// Strategy: one block per (b,h) image row. Stage ALL 3 channels of both image
// rows into shared memory with 6 front-batched float4 LDGs (deep MLP, one
// barrier), then serve every bilinear tap and pass-through read from LDS.
// L1tex sees only coalesced float4 traffic; DRAM streams without per-channel
// pipeline drains.

#define BATCH 8
#define CH 3
#define HH 1024
#define WW 1920
#define MAXD 128.0f

__global__ __launch_bounds__(480) void stereo_denoise_kernel(
    const float* __restrict__ img_l,
    const float* __restrict__ img_r,
    const float* __restrict__ depth,
    float* __restrict__ out)
{
    __shared__ float sl[CH * WW];   // 23040 B
    __shared__ float sr[CH * WW];   // 23040 B  (total 46080 < 48K static limit)

    const int row = blockIdx.x;          // b*HH + h
    const int b   = row / HH;
    const int u   = threadIdx.x;         // 0..479
    const int w0  = u * 4;

    const int HW = HH * WW;
    const int N  = BATCH * CH * HW;          // 47,185,920 (fits int32)
    const int plane0 = b * (CH - 1) * HW + row * WW;   // == b*CH*HW + h*WW

    // ---- stage all channels of both rows: 6 independent float4 LDGs ----
#pragma unroll
    for (int c = 0; c < CH; ++c) {
        *reinterpret_cast<float4*>(sl + c * WW + w0) =
            *reinterpret_cast<const float4*>(img_l + plane0 + c * HW + w0);
        *reinterpret_cast<float4*>(sr + c * WW + w0) =
            *reinterpret_cast<const float4*>(img_r + plane0 + c * HW + w0);
    }

    // ---- per-pixel warp indices/weights (channel-invariant) ----
    float4 dep = *reinterpret_cast<const float4*>(depth + (size_t)row * WW + w0);
    float d[4] = {dep.x, dep.y, dep.z, dep.w};

    int   i0L[4], i0R[4];
    float fL[4], fR[4];
#pragma unroll
    for (int p = 0; p < 4; ++p) {
        float disp = fminf(fmaxf(d[p] * MAXD, 0.0f), MAXD);
        float xw = (float)(w0 + p);

        float xl = fminf(fmaxf(xw - disp, 0.0f), (float)(WW - 1));
        int i0 = (int)xl;                    // xl >= 0 -> trunc == floor
        fL[p]  = xl - (float)i0;
        i0L[p] = i0;

        float xr = fminf(fmaxf(xw + disp, 0.0f), (float)(WW - 1));
        int j0 = (int)xr;
        fR[p]  = xr - (float)j0;
        i0R[p] = j0;
    }

    __syncthreads();                         // single barrier per block

#pragma unroll
    for (int c = 0; c < CH; ++c) {
        const int base = plane0 + c * HW;
        const float* slc = sl + c * WW;
        const float* src = sr + c * WW;

        // pass-through terms from smem (conflict-free LDS.128)
        float4 lv = *reinterpret_cast<const float4*>(slc + w0);
        float4 rv = *reinterpret_cast<const float4*>(src + w0);
        float lvv[4] = {lv.x, lv.y, lv.z, lv.w};
        float rvv[4] = {rv.x, rv.y, rv.z, rv.w};

        float ol[4], og[4];
#pragma unroll
        for (int p = 0; p < 4; ++p) {
            int a0 = i0L[p];
            int a1 = min(a0 + 1, WW - 1);
            int b0 = i0R[p];
            int b1 = min(b0 + 1, WW - 1);
            float wr = src[a0] * (1.0f - fL[p]) + src[a1] * fL[p];
            float wl = slc[b0] * (1.0f - fR[p]) + slc[b1] * fR[p];
            ol[p] = (lvv[p] + wr) * 0.5f;
            og[p] = (rvv[p] + wl) * 0.5f;
        }

        *reinterpret_cast<float4*>(out + base + w0) =
            make_float4(ol[0], ol[1], ol[2], ol[3]);
        *reinterpret_cast<float4*>(out + N + base + w0) =
            make_float4(og[0], og[1], og[2], og[3]);
    }
}

extern "C" void kernel_launch(void* const* d_in, const int* in_sizes, int n_in,
                              void* d_out, int out_size) {
    const float* img_l = (const float*)d_in[0];
    const float* img_r = (const float*)d_in[1];
    const float* depth = (const float*)d_in[2];
    float* out = (float*)d_out;

    const int blocks = BATCH * HH;           // one block per image row
    stereo_denoise_kernel<<<blocks, 480>>>(img_l, img_r, depth, out);
}

// round 9
// speedup vs baseline: 1.0289x; 1.0289x over previous
#include <cuda_runtime.h>
#include <cstdint>

// StereoDenoiser: B=8, C=3, H=1024, W=1920, fp32.
//   disp  = clip(depth*128, 0, 128)            [B,H,W]
//   warped_r = bilinear_x(img_r, x = w - disp) (border clamp)
//   warped_l = bilinear_x(img_l, x = w + disp)
//   out_l = (img_l + warped_r)*0.5 ; out_r = (img_r + warped_l)*0.5
// Output buffer: [out_l | out_r], each B*C*H*W floats.
//
// Strategy: one block per (b,h) image row. Double-buffered cp.async pipeline
// stages channel c+1's rows (both images) GMEM->SMEM while channel c computes.
// All bilinear taps + pass-through reads served from LDS; L1tex sees only
// coalesced 16B traffic; DRAM streams continuously.

#define BATCH 8
#define CH 3
#define HH 1024
#define WW 1920
#define MAXD 128.0f

__device__ __forceinline__ void cp_async16(float* smem_dst, const float* gsrc) {
    unsigned int s = (unsigned int)__cvta_generic_to_shared(smem_dst);
    asm volatile("cp.async.cg.shared.global [%0], [%1], 16;" :: "r"(s), "l"(gsrc));
}

__global__ __launch_bounds__(480) void stereo_denoise_kernel(
    const float* __restrict__ img_l,
    const float* __restrict__ img_r,
    const float* __restrict__ depth,
    float* __restrict__ out)
{
    __shared__ float sl[2][WW];   // 15360 B
    __shared__ float sr[2][WW];   // 15360 B  (total 30720 B)

    const int row = blockIdx.x;          // b*HH + h
    const int b   = row / HH;
    const int u   = threadIdx.x;         // 0..479
    const int w0  = u * 4;

    const int HW = HH * WW;
    const int N  = BATCH * CH * HW;                    // 47,185,920 (fits int32)
    const int plane0 = b * (CH - 1) * HW + row * WW;   // == b*CH*HW + h*WW

    // ---- prefetch channel 0 ----
    cp_async16(&sl[0][w0], img_l + plane0 + w0);
    cp_async16(&sr[0][w0], img_r + plane0 + w0);
    asm volatile("cp.async.commit_group;");

    // ---- per-pixel warp indices/weights (channel-invariant), overlapped ----
    float4 dep = *reinterpret_cast<const float4*>(depth + (size_t)row * WW + w0);
    float d[4] = {dep.x, dep.y, dep.z, dep.w};

    int   i0L[4], i0R[4];
    float fL[4], fR[4];
#pragma unroll
    for (int p = 0; p < 4; ++p) {
        float disp = fminf(fmaxf(d[p] * MAXD, 0.0f), MAXD);
        float xw = (float)(w0 + p);

        float xl = fminf(fmaxf(xw - disp, 0.0f), (float)(WW - 1));
        int i0 = (int)xl;                    // xl >= 0 -> trunc == floor
        fL[p]  = xl - (float)i0;
        i0L[p] = i0;

        float xr = fminf(fmaxf(xw + disp, 0.0f), (float)(WW - 1));
        int j0 = (int)xr;
        fR[p]  = xr - (float)j0;
        i0R[p] = j0;
    }

#pragma unroll
    for (int c = 0; c < CH; ++c) {
        // prefetch next channel into the other buffer
        if (c + 1 < CH) {
            const int nbase = plane0 + (c + 1) * HW;
            cp_async16(&sl[(c + 1) & 1][w0], img_l + nbase + w0);
            cp_async16(&sr[(c + 1) & 1][w0], img_r + nbase + w0);
            asm volatile("cp.async.commit_group;");
            asm volatile("cp.async.wait_group 1;");   // channel c's group done
        } else {
            asm volatile("cp.async.wait_group 0;");
        }
        __syncthreads();

        const float* slc = sl[c & 1];
        const float* src = sr[c & 1];

        // pass-through terms from smem (conflict-free LDS.128)
        float4 lv = *reinterpret_cast<const float4*>(slc + w0);
        float4 rv = *reinterpret_cast<const float4*>(src + w0);
        float lvv[4] = {lv.x, lv.y, lv.z, lv.w};
        float rvv[4] = {rv.x, rv.y, rv.z, rv.w};

        float ol[4], og[4];
#pragma unroll
        for (int p = 0; p < 4; ++p) {
            int a0 = i0L[p];
            int a1 = min(a0 + 1, WW - 1);
            int b0 = i0R[p];
            int b1 = min(b0 + 1, WW - 1);
            float wr = src[a0] * (1.0f - fL[p]) + src[a1] * fL[p];
            float wl = slc[b0] * (1.0f - fR[p]) + slc[b1] * fR[p];
            ol[p] = (lvv[p] + wr) * 0.5f;
            og[p] = (rvv[p] + wl) * 0.5f;
        }

        const int base = plane0 + c * HW;
        *reinterpret_cast<float4*>(out + base + w0) =
            make_float4(ol[0], ol[1], ol[2], ol[3]);
        *reinterpret_cast<float4*>(out + N + base + w0) =
            make_float4(og[0], og[1], og[2], og[3]);

        // next iteration's cp.async writes buf[c&1] (the one just read) —
        // barrier before that issue.
        if (c + 1 < CH) __syncthreads();
    }
}

extern "C" void kernel_launch(void* const* d_in, const int* in_sizes, int n_in,
                              void* d_out, int out_size) {
    const float* img_l = (const float*)d_in[0];
    const float* img_r = (const float*)d_in[1];
    const float* depth = (const float*)d_in[2];
    float* out = (float*)d_out;

    const int blocks = BATCH * HH;           // one block per image row
    stereo_denoise_kernel<<<blocks, 480>>>(img_l, img_r, depth, out);
}